// round 13
// baseline (speedup 1.0000x reference)
#include <cuda.h>
#include <cuda_runtime.h>

#define FIN 512
#define HID 16
#define CO  7
#define NMAX 200000

// Scratch (no allocations allowed -> __device__ globals)
__device__ float g_deg [NMAX];
__device__ float g_dinv[NMAX];
__device__ float g_g1  [NMAX * HID];   // (x@W1) * dinv[row]
__device__ float g_t1  [NMAX * HID];   // scatter-add accumulator, layer 1
__device__ float g_g2  [NMAX * 8];     // (relu(out1)@W2) * dinv[row], padded to 8
__device__ float g_t2  [NMAX * 8];     // scatter-add accumulator, layer 2

typedef unsigned long long ull;

// ---------- helpers ----------
__device__ __forceinline__ void red4(float* p, float4 v) {
    asm volatile("red.global.add.v4.f32 [%0], {%1,%2,%3,%4};"
                 :: "l"(p), "f"(v.x), "f"(v.y), "f"(v.z), "f"(v.w) : "memory");
}
__device__ __forceinline__ void red1(float* p, float v) {
    asm volatile("red.global.add.f32 [%0], %1;" :: "l"(p), "f"(v) : "memory");
}
__device__ __forceinline__ ull fma2(ull a, ull b, ull c) {
    ull d;
    asm("fma.rn.f32x2 %0, %1, %2, %3;" : "=l"(d) : "l"(a), "l"(b), "l"(c));
    return d;
}
__device__ __forceinline__ ull pack2(float v) {
    ull r;
    asm("mov.b64 %0, {%1, %1};" : "=l"(r) : "f"(v));
    return r;
}
__device__ __forceinline__ float lo32(ull v) {
    return __uint_as_float((unsigned)(v & 0xffffffffull));
}
__device__ __forceinline__ float hi32(ull v) {
    return __uint_as_float((unsigned)(v >> 32));
}
__device__ __forceinline__ void mbar_init(unsigned a, int cnt) {
    asm volatile("mbarrier.init.shared.b64 [%0], %1;" :: "r"(a), "r"(cnt) : "memory");
}
__device__ __forceinline__ void mbar_expect(unsigned a, int tx) {
    asm volatile("mbarrier.arrive.expect_tx.shared.b64 _, [%0], %1;"
                 :: "r"(a), "r"(tx) : "memory");
}
__device__ __forceinline__ void mbar_wait(unsigned a, int ph) {
    asm volatile(
        "{\n\t.reg .pred P;\n\t"
        "W_%=:\n\t"
        "mbarrier.try_wait.parity.acquire.cta.shared::cta.b64 P, [%0], %1, 0x989680;\n\t"
        "@!P bra W_%=;\n\t}"
        :: "r"(a), "r"(ph) : "memory");
}
__device__ __forceinline__ void tma2d(unsigned dst, const CUtensorMap* m,
                                      int cx, int cy, unsigned mbar) {
    asm volatile("cp.async.bulk.tensor.2d.shared::cta.global.tile."
                 "mbarrier::complete_tx::bytes [%0], [%1, {%2, %3}], [%4];"
                 :: "r"(dst), "l"(m), "r"(cx), "r"(cy), "r"(mbar) : "memory");
}

// ---------- kernels ----------
// zero accumulators, deg = 1 (self loop)
__global__ void k_init(int n) {
    int i = blockIdx.x * blockDim.x + threadIdx.x;
    int total = n * HID;
    if (i < total)  g_t1[i] = 0.0f;
    if (i < n * 8)  g_t2[i] = 0.0f;
    if (i < n)      g_deg[i] = 1.0f;
}

__global__ void k_deg(const int* __restrict__ dst, int E) {
    int i = blockIdx.x * blockDim.x + threadIdx.x;
    if (i < E) red1(&g_deg[dst[i]], 1.0f);
}

__global__ void k_dinv(int n) {
    int i = blockIdx.x * blockDim.x + threadIdx.x;
    if (i < n) g_dinv[i] = rsqrtf(g_deg[i]);   // deg >= 1 always
}

// ---------------------------------------------------------------------------
// g1[row] = (x[row] @ W1) * dinv[row]
// 128 threads = 128 rows/CTA, 1 row/thread. x delivered by TMA 2D tile loads:
// ONE UTMALDG per [32-float x 128-row] 16 KB tile (no per-row/per-128B op
// cost). SW128 swizzle -> per-phase <=2-way LDS conflicts on x reads.
// W1 in smem, warp-uniform broadcast LDS.128. Ring of 4 slots, mbarrier +
// expect_tx, depth-4 prefetch. ~96 KB smem -> 2 CTAs/SM.
// ---------------------------------------------------------------------------
#define XB     128
#define KT     32               // k per tile (128 bytes/row = SW128 atom)
#define NT     (FIN / KT)       // 16 tiles
#define NSTG   4
#define SLOTB  (XB * 128)       // 16384 B per slot
// smem bytes: [0,128) mbarriers | [128, 128+32768) W1 | align 1024 | 4 slots
#define XSMEM  (128 + FIN * HID * 4 + 1024 + NSTG * SLOTB)

__global__ void __launch_bounds__(XB) k_xform(const __grid_constant__ CUtensorMap tmap,
                                              const float* __restrict__ W1, int n) {
    extern __shared__ float smem[];
    const int tid = threadIdx.x;
    const int rowBase = blockIdx.x * XB;

    unsigned sbase = (unsigned)__cvta_generic_to_shared(smem);
    unsigned mb    = sbase;                           // 4 mbarriers, 8 B each

    // stage W1 (2048 float4, 16 per thread)
    float4* Wst = (float4*)((char*)smem + 128);
#pragma unroll
    for (int i = 0; i < 16; i++)
        Wst[i * XB + tid] = __ldg(&((const float4*)W1)[i * XB + tid]);
    const ulonglong2* W128 = (const ulonglong2*)((char*)smem + 128);

    unsigned slotBase = (sbase + 128u + (unsigned)(FIN * HID * 4) + 1023u) & ~1023u;
    const char* slotPtr = (const char*)smem + (slotBase - sbase);

    if (tid == 0) {
#pragma unroll
        for (int s = 0; s < NSTG; s++) mbar_init(mb + 8 * s, 1);
    }
    __syncthreads();   // mbarriers + W visible

    // prologue: one 16 KB TMA per slot, tiles 0..3
    if (tid == 0) {
#pragma unroll
        for (int s = 0; s < NSTG; s++) {
            mbar_expect(mb + 8 * s, SLOTB);
            tma2d(slotBase + (unsigned)s * SLOTB, &tmap, s * KT, rowBase, mb + 8 * s);
        }
    }

    ull acc[8];
#pragma unroll
    for (int p = 0; p < 8; p++) acc[p] = 0ull;

    const unsigned xorv = (unsigned)(tid & 7) * 16u;  // SW128 granule XOR
    int ph = 0;
#pragma unroll 1
    for (int t = 0; t < NT; t++) {
        int s = t & (NSTG - 1);
        mbar_wait(mb + 8 * s, ph);
        if (s == NSTG - 1) ph ^= 1;

        const char* xrow = slotPtr + s * SLOTB + tid * 128;
        int kt = t * KT;
#pragma unroll
        for (int g = 0; g < 8; g++) {
            float4 xq = *(const float4*)(xrow + (((unsigned)g * 16u) ^ xorv));
            float xa[4];
            *(float4*)xa = xq;
#pragma unroll
            for (int c = 0; c < 4; c++) {
                int k = kt + 4 * g + c;
                ull x2 = pack2(xa[c]);
                ulonglong2 wA = W128[k * 4 + 0];   // warp-uniform broadcast
                ulonglong2 wB = W128[k * 4 + 1];
                ulonglong2 wC = W128[k * 4 + 2];
                ulonglong2 wD = W128[k * 4 + 3];
                acc[0] = fma2(x2, wA.x, acc[0]);
                acc[1] = fma2(x2, wA.y, acc[1]);
                acc[2] = fma2(x2, wB.x, acc[2]);
                acc[3] = fma2(x2, wB.y, acc[3]);
                acc[4] = fma2(x2, wC.x, acc[4]);
                acc[5] = fma2(x2, wC.y, acc[5]);
                acc[6] = fma2(x2, wD.x, acc[6]);
                acc[7] = fma2(x2, wD.y, acc[7]);
            }
        }

        __syncthreads();                              // slot s fully consumed
        if (tid == 0 && t + NSTG < NT) {
            mbar_expect(mb + 8 * s, SLOTB);
            tma2d(slotBase + (unsigned)s * SLOTB, &tmap,
                  (t + NSTG) * KT, rowBase, mb + 8 * s);
        }
    }

    int grow = rowBase + tid;
    if (grow < n) {
        float d = g_dinv[grow];
        float o[16];
#pragma unroll
        for (int p = 0; p < 8; p++) {
            o[2 * p]     = lo32(acc[p]) * d;
            o[2 * p + 1] = hi32(acc[p]) * d;
        }
        float4* dst4 = (float4*)&g_g1[(size_t)grow * HID];
#pragma unroll
        for (int v = 0; v < 4; v++) dst4[v] = *(float4*)&o[4 * v];
    }
}

// scatter-add g1[src] into t1[dst] — 4 threads per edge (16B each).
__global__ void k_agg1(const int* __restrict__ src, const int* __restrict__ dst, int E) {
    int i = blockIdx.x * blockDim.x + threadIdx.x;
    int e = i >> 2;
    if (e >= E) return;
    int j = i & 3;
    int s = src[e], d = dst[e];
    float4 v = __ldg((const float4*)&g_g1[(size_t)s * HID] + j);
    red4((float*)((float4*)&g_t1[(size_t)d * HID] + j), v);
}

// out1 = relu(dinv*(t1 + g1) + b1);  g2 = (out1 @ W2) * dinv
__global__ void k_mid(const float* __restrict__ W2, const float* __restrict__ b1, int n) {
    int i = blockIdx.x * blockDim.x + threadIdx.x;
    if (i >= n) return;
    float d = g_dinv[i];
    float h[16];
#pragma unroll
    for (int q = 0; q < 4; q++) {
        float4 tv = *(const float4*)&g_t1[(size_t)i * HID + 4 * q];
        float4 gv = *(const float4*)&g_g1[(size_t)i * HID + 4 * q];
        h[4 * q + 0] = fmaxf(d * (tv.x + gv.x) + __ldg(&b1[4 * q + 0]), 0.0f);
        h[4 * q + 1] = fmaxf(d * (tv.y + gv.y) + __ldg(&b1[4 * q + 1]), 0.0f);
        h[4 * q + 2] = fmaxf(d * (tv.z + gv.z) + __ldg(&b1[4 * q + 2]), 0.0f);
        h[4 * q + 3] = fmaxf(d * (tv.w + gv.w) + __ldg(&b1[4 * q + 3]), 0.0f);
    }
    float o[CO];
#pragma unroll
    for (int j = 0; j < CO; j++) o[j] = 0.0f;
#pragma unroll
    for (int k = 0; k < HID; k++)
#pragma unroll
        for (int j = 0; j < CO; j++)
            o[j] = fmaf(h[k], __ldg(&W2[k * CO + j]), o[j]);
    float out8[8];
#pragma unroll
    for (int j = 0; j < CO; j++) out8[j] = o[j] * d;
    out8[7] = 0.0f;
    float4* dst4 = (float4*)&g_g2[(size_t)i * 8];
    dst4[0] = *(float4*)&out8[0];
    dst4[1] = *(float4*)&out8[4];
}

// scatter-add g2[src] into t2[dst] — 2 threads per edge (16B each).
__global__ void k_agg2(const int* __restrict__ src, const int* __restrict__ dst, int E) {
    int i = blockIdx.x * blockDim.x + threadIdx.x;
    int e = i >> 1;
    if (e >= E) return;
    int j = i & 1;
    int s = src[e], d = dst[e];
    float4 v = __ldg((const float4*)&g_g2[(size_t)s * 8] + j);
    red4((float*)((float4*)&g_t2[(size_t)d * 8] + j), v);
}

// out = dinv*(t2 + g2) + b2
__global__ void k_final(const float* __restrict__ b2, float* __restrict__ out, int n) {
    int i = blockIdx.x * blockDim.x + threadIdx.x;
    if (i >= n) return;
    float d = g_dinv[i];
#pragma unroll
    for (int j = 0; j < CO; j++)
        out[(size_t)i * CO + j] =
            d * (g_t2[(size_t)i * 8 + j] + g_g2[(size_t)i * 8 + j]) + __ldg(&b2[j]);
}

// ---------- host: tensor-map encode via runtime entry point (no -lcuda) ----
typedef CUresult (*tme_fn_t)(CUtensorMap*, CUtensorMapDataType, cuuint32_t, void*,
                             const cuuint64_t*, const cuuint64_t*, const cuuint32_t*,
                             const cuuint32_t*, CUtensorMapInterleave, CUtensorMapSwizzle,
                             CUtensorMapL2promotion, CUtensorMapFloatOOBfill);

static tme_fn_t get_encoder() {
    static tme_fn_t fn = nullptr;
    if (!fn) {
        void* p = nullptr;
        cudaDriverEntryPointQueryResult st;
#if CUDART_VERSION >= 12050
        cudaGetDriverEntryPointByVersion("cuTensorMapEncodeTiled", &p, 12000,
                                         cudaEnableDefault, &st);
#else
        cudaGetDriverEntryPoint("cuTensorMapEncodeTiled", &p, cudaEnableDefault, &st);
#endif
        fn = (tme_fn_t)p;
    }
    return fn;
}

// ---------- launch ----------
extern "C" void kernel_launch(void* const* d_in, const int* in_sizes, int n_in,
                              void* d_out, int out_size) {
    const float* x  = (const float*)d_in[0];
    const int*   ei = (const int*)  d_in[1];
    const float* W1 = (const float*)d_in[2];
    const float* b1 = (const float*)d_in[3];
    const float* W2 = (const float*)d_in[4];
    const float* b2 = (const float*)d_in[5];

    int n = in_sizes[0] / FIN;
    int E = in_sizes[1] / 2;
    const int* src = ei;
    const int* dst = ei + E;

    // Encode TMA descriptor for x: [FIN contiguous] x [n rows], box [KT,128],
    // SW128 (box row = 128 B = swizzle atom). Pure host-side computation.
    CUtensorMap tmap;
    {
        cuuint64_t dims[2]    = {(cuuint64_t)FIN, (cuuint64_t)n};
        cuuint64_t strides[1] = {(cuuint64_t)FIN * 4};
        cuuint32_t box[2]     = {KT, XB};
        cuuint32_t es[2]      = {1, 1};
        get_encoder()(&tmap, CU_TENSOR_MAP_DATA_TYPE_FLOAT32, 2, (void*)x,
                      dims, strides, box, es,
                      CU_TENSOR_MAP_INTERLEAVE_NONE, CU_TENSOR_MAP_SWIZZLE_128B,
                      CU_TENSOR_MAP_L2_PROMOTION_L2_128B,
                      CU_TENSOR_MAP_FLOAT_OOB_FILL_NONE);
    }

    const int TB = 256;
    int gInit  = (n * HID + TB - 1) / TB;
    int gEdge  = (E + TB - 1) / TB;
    int gEdge4 = (4 * E + TB - 1) / TB;
    int gEdge2 = (2 * E + TB - 1) / TB;
    int gNode  = (n + TB - 1) / TB;
    int gXform = (n + XB - 1) / XB;

    static int smem_set = 0;
    if (!smem_set) {
        cudaFuncSetAttribute(k_xform, cudaFuncAttributeMaxDynamicSharedMemorySize, XSMEM);
        smem_set = 1;
    }

    k_init <<<gInit,  TB>>>(n);
    k_deg  <<<gEdge,  TB>>>(dst, E);
    k_dinv <<<gNode,  TB>>>(n);
    k_xform<<<gXform, XB, XSMEM>>>(tmap, W1, n);
    k_agg1 <<<gEdge4, TB>>>(src, dst, E);
    k_mid  <<<gNode,  TB>>>(W2, b1, n);
    k_agg2 <<<gEdge2, TB>>>(src, dst, E);
    k_final<<<gNode,  TB>>>(b2, (float*)d_out, n);
}

// round 15
// speedup vs baseline: 1.7589x; 1.7589x over previous
#include <cuda.h>
#include <cuda_runtime.h>

#define FIN 512
#define HID 16
#define CO  7
#define NMAX 200000

// Scratch (no allocations allowed -> __device__ globals)
__device__ float g_deg [NMAX];
__device__ float g_dinv[NMAX];
__device__ float g_g1  [NMAX * HID];   // (x@W1) * dinv[row]
__device__ float g_t1  [NMAX * HID];   // scatter-add accumulator, layer 1
__device__ float g_g2  [NMAX * 8];     // (relu(out1)@W2) * dinv[row], padded to 8
__device__ float g_t2  [NMAX * 8];     // scatter-add accumulator, layer 2

typedef unsigned long long ull;

// ---------- helpers ----------
__device__ __forceinline__ void red4(float* p, float4 v) {
    asm volatile("red.global.add.v4.f32 [%0], {%1,%2,%3,%4};"
                 :: "l"(p), "f"(v.x), "f"(v.y), "f"(v.z), "f"(v.w) : "memory");
}
__device__ __forceinline__ void red1(float* p, float v) {
    asm volatile("red.global.add.f32 [%0], %1;" :: "l"(p), "f"(v) : "memory");
}
__device__ __forceinline__ void mbar_init(unsigned a, int cnt) {
    asm volatile("mbarrier.init.shared.b64 [%0], %1;" :: "r"(a), "r"(cnt) : "memory");
}
__device__ __forceinline__ void mbar_expect(unsigned a, int tx) {
    asm volatile("mbarrier.arrive.expect_tx.shared.b64 _, [%0], %1;"
                 :: "r"(a), "r"(tx) : "memory");
}
__device__ __forceinline__ void mbar_wait(unsigned a, int ph) {
    asm volatile(
        "{\n\t.reg .pred P;\n\t"
        "W_%=:\n\t"
        "mbarrier.try_wait.parity.acquire.cta.shared::cta.b64 P, [%0], %1, 0x989680;\n\t"
        "@!P bra W_%=;\n\t}"
        :: "r"(a), "r"(ph) : "memory");
}
__device__ __forceinline__ void tma2d(unsigned dst, const CUtensorMap* m,
                                      int cx, int cy, unsigned mbar) {
    asm volatile("cp.async.bulk.tensor.2d.shared::cta.global.tile."
                 "mbarrier::complete_tx::bytes [%0], [%1, {%2, %3}], [%4];"
                 :: "r"(dst), "l"(m), "r"(cx), "r"(cy), "r"(mbar) : "memory");
}
__device__ __forceinline__ unsigned f2tf32(float f) {
    unsigned r;
    asm("cvt.rna.tf32.f32 %0, %1;" : "=r"(r) : "f"(f));
    return r;
}
// Ampere-class warp MMA: m16n8k8 tf32 (valid on sm_103; no tcgen05 features)
__device__ __forceinline__ void mma_tf32(float* d, const unsigned* a, const unsigned* b) {
    asm volatile(
        "mma.sync.aligned.m16n8k8.row.col.f32.tf32.tf32.f32 "
        "{%0,%1,%2,%3}, {%4,%5,%6,%7}, {%8,%9}, {%0,%1,%2,%3};"
        : "+f"(d[0]), "+f"(d[1]), "+f"(d[2]), "+f"(d[3])
        : "r"(a[0]), "r"(a[1]), "r"(a[2]), "r"(a[3]), "r"(b[0]), "r"(b[1]));
}

// ---------- kernels ----------
// zero accumulators, deg = 1 (self loop)
__global__ void k_init(int n) {
    int i = blockIdx.x * blockDim.x + threadIdx.x;
    int total = n * HID;
    if (i < total)  g_t1[i] = 0.0f;
    if (i < n * 8)  g_t2[i] = 0.0f;
    if (i < n)      g_deg[i] = 1.0f;
}

__global__ void k_deg(const int* __restrict__ dst, int E) {
    int i = blockIdx.x * blockDim.x + threadIdx.x;
    if (i < E) red1(&g_deg[dst[i]], 1.0f);
}

__global__ void k_dinv(int n) {
    int i = blockIdx.x * blockDim.x + threadIdx.x;
    if (i < n) g_dinv[i] = rsqrtf(g_deg[i]);   // deg >= 1 always
}

// ---------------------------------------------------------------------------
// g1[row] = (x[row] @ W1) * dinv[row]  -- warp-level tf32 mma.sync GEMM.
// 256 threads = 8 warps; warp w owns rows [16w,16w+16) of the CTA's 128 rows.
// x: TMA SW128 tiles [32k x 128 rows] (16 KB), ring of 4 slots + mbarrier.
// W1: staged once to smem pre-rounded to tf32, pad-17 rows (conflict-spread).
// Per warp-tile: 32 LDS.32 + 16 cvt + 8 HMMA -- issue/L1 walls gone;
// kernel is DRAM-bound (~51 us floor).
// ---------------------------------------------------------------------------
#define XB     256
#define XROWS  128
#define KT     32                    // k per TMA tile (128 B rows)
#define NT     (FIN / KT)            // 16 tiles
#define NSTG   4
#define SLOTB  (XROWS * 128)         // 16384 B
#define OFF_SLOT 1024
#define OFF_W    (OFF_SLOT + NSTG * SLOTB)        // 66560
#define XSMEM    (OFF_W + FIN * 17 * 4)           // 101376 B

__global__ void __launch_bounds__(XB) k_xform(const __grid_constant__ CUtensorMap tmap,
                                              const float* __restrict__ W1, int n) {
    extern __shared__ float smem[];
    const int tid  = threadIdx.x;
    const int wid  = tid >> 5;
    const int lane = tid & 31;
    const int g    = lane >> 2;        // group id (row/col within fragment)
    const int t4   = lane & 3;         // thread-in-group
    const int rowBase = blockIdx.x * XROWS;

    unsigned sbase = (unsigned)__cvta_generic_to_shared(smem);

    // stage W1 -> smem as tf32 bits, [k][17] layout (odd stride: spread banks)
    unsigned* Wu = (unsigned*)((char*)smem + OFF_W);
    for (int i = tid; i < FIN * HID; i += XB) {
        int k = i >> 4, nn = i & 15;
        Wu[k * 17 + nn] = f2tf32(W1[i]);
    }

    if (tid == 0)
#pragma unroll
        for (int s = 0; s < NSTG; s++) mbar_init(sbase + 8 * s, 1);
    __syncthreads();   // W staged + barriers visible

    // prologue: fill all 4 slots (one 16 KB UTMALDG each)
    if (tid == 0) {
#pragma unroll
        for (int s = 0; s < NSTG; s++) {
            mbar_expect(sbase + 8 * s, SLOTB);
            tma2d(sbase + OFF_SLOT + (unsigned)s * SLOTB, &tmap, s * KT, rowBase,
                  sbase + 8 * s);
        }
    }

    float acc[2][4] = {{0.f, 0.f, 0.f, 0.f}, {0.f, 0.f, 0.f, 0.f}};
    const int ra = wid * 16 + g;       // CTA-local row of a0/a2 (rb = ra+8)
    const char* slot0 = (const char*)smem + OFF_SLOT;

#pragma unroll 1
    for (int t = 0; t < NT; t++) {
        int s  = t & (NSTG - 1);
        int ph = (t >> 2) & 1;
        mbar_wait(sbase + 8 * s, ph);

        const char* tile = slot0 + s * SLOTB;
        int kt = t * KT;
#pragma unroll
        for (int kst = 0; kst < 4; kst++) {            // 4 x k8 steps
            int c0 = kst * 8 + t4;                     // col in 32-float row
            // A fragment (rows ra, ra+8; cols c0, c0+4), SW128 addressing
            unsigned ax0 = (unsigned)(ra * 128)       + (((unsigned)(c0 * 4)) ^ ((unsigned)(ra & 7) * 16u));
            unsigned ax1 = (unsigned)((ra + 8) * 128) + (((unsigned)(c0 * 4)) ^ ((unsigned)(ra & 7) * 16u));
            unsigned a[4];
            a[0] = f2tf32(*(const float*)(tile + ax0));
            a[1] = f2tf32(*(const float*)(tile + ax1));
            a[2] = f2tf32(*(const float*)(tile + (ax0 ^ 16u)));
            a[3] = f2tf32(*(const float*)(tile + (ax1 ^ 16u)));
            // B fragments from W smem (already tf32)
            int kb = kt + kst * 8 + t4;
#pragma unroll
            for (int nt = 0; nt < 2; nt++) {
                unsigned b[2];
                b[0] = Wu[kb * 17 + nt * 8 + g];
                b[1] = Wu[(kb + 4) * 17 + nt * 8 + g];
                mma_tf32(acc[nt], a, b);
            }
        }

        __syncthreads();                               // slot s fully consumed
        if (tid == 0 && t + NSTG < NT) {
            mbar_expect(sbase + 8 * s, SLOTB);
            tma2d(sbase + OFF_SLOT + (unsigned)s * SLOTB, &tmap,
                  (t + NSTG) * KT, rowBase, sbase + 8 * s);
        }
    }

    // epilogue: c0,c1 -> row ra cols (2t4, 2t4+1); c2,c3 -> row ra+8
    int gra = rowBase + ra, grb = gra + 8;
    if (gra < n) {
        float d = g_dinv[gra];
#pragma unroll
        for (int nt = 0; nt < 2; nt++) {
            float2 v = make_float2(acc[nt][0] * d, acc[nt][1] * d);
            *(float2*)&g_g1[(size_t)gra * HID + nt * 8 + 2 * t4] = v;
        }
    }
    if (grb < n) {
        float d = g_dinv[grb];
#pragma unroll
        for (int nt = 0; nt < 2; nt++) {
            float2 v = make_float2(acc[nt][2] * d, acc[nt][3] * d);
            *(float2*)&g_g1[(size_t)grb * HID + nt * 8 + 2 * t4] = v;
        }
    }
}

// scatter-add g1[src] into t1[dst] — 4 threads per edge (16B each).
__global__ void k_agg1(const int* __restrict__ src, const int* __restrict__ dst, int E) {
    int i = blockIdx.x * blockDim.x + threadIdx.x;
    int e = i >> 2;
    if (e >= E) return;
    int j = i & 3;
    int s = src[e], d = dst[e];
    float4 v = __ldg((const float4*)&g_g1[(size_t)s * HID] + j);
    red4((float*)((float4*)&g_t1[(size_t)d * HID] + j), v);
}

// out1 = relu(dinv*(t1 + g1) + b1);  g2 = (out1 @ W2) * dinv
__global__ void k_mid(const float* __restrict__ W2, const float* __restrict__ b1, int n) {
    int i = blockIdx.x * blockDim.x + threadIdx.x;
    if (i >= n) return;
    float d = g_dinv[i];
    float h[16];
#pragma unroll
    for (int q = 0; q < 4; q++) {
        float4 tv = *(const float4*)&g_t1[(size_t)i * HID + 4 * q];
        float4 gv = *(const float4*)&g_g1[(size_t)i * HID + 4 * q];
        h[4 * q + 0] = fmaxf(d * (tv.x + gv.x) + __ldg(&b1[4 * q + 0]), 0.0f);
        h[4 * q + 1] = fmaxf(d * (tv.y + gv.y) + __ldg(&b1[4 * q + 1]), 0.0f);
        h[4 * q + 2] = fmaxf(d * (tv.z + gv.z) + __ldg(&b1[4 * q + 2]), 0.0f);
        h[4 * q + 3] = fmaxf(d * (tv.w + gv.w) + __ldg(&b1[4 * q + 3]), 0.0f);
    }
    float o[CO];
#pragma unroll
    for (int j = 0; j < CO; j++) o[j] = 0.0f;
#pragma unroll
    for (int k = 0; k < HID; k++)
#pragma unroll
        for (int j = 0; j < CO; j++)
            o[j] = fmaf(h[k], __ldg(&W2[k * CO + j]), o[j]);
    float out8[8];
#pragma unroll
    for (int j = 0; j < CO; j++) out8[j] = o[j] * d;
    out8[7] = 0.0f;
    float4* dst4 = (float4*)&g_g2[(size_t)i * 8];
    dst4[0] = *(float4*)&out8[0];
    dst4[1] = *(float4*)&out8[4];
}

// scatter-add g2[src] into t2[dst] — 2 threads per edge (16B each).
__global__ void k_agg2(const int* __restrict__ src, const int* __restrict__ dst, int E) {
    int i = blockIdx.x * blockDim.x + threadIdx.x;
    int e = i >> 1;
    if (e >= E) return;
    int j = i & 1;
    int s = src[e], d = dst[e];
    float4 v = __ldg((const float4*)&g_g2[(size_t)s * 8] + j);
    red4((float*)((float4*)&g_t2[(size_t)d * 8] + j), v);
}

// out = dinv*(t2 + g2) + b2
__global__ void k_final(const float* __restrict__ b2, float* __restrict__ out, int n) {
    int i = blockIdx.x * blockDim.x + threadIdx.x;
    if (i >= n) return;
    float d = g_dinv[i];
#pragma unroll
    for (int j = 0; j < CO; j++)
        out[(size_t)i * CO + j] =
            d * (g_t2[(size_t)i * 8 + j] + g_g2[(size_t)i * 8 + j]) + __ldg(&b2[j]);
}

// ---------- host: tensor-map encode via runtime entry point (no -lcuda) ----
typedef CUresult (*tme_fn_t)(CUtensorMap*, CUtensorMapDataType, cuuint32_t, void*,
                             const cuuint64_t*, const cuuint64_t*, const cuuint32_t*,
                             const cuuint32_t*, CUtensorMapInterleave, CUtensorMapSwizzle,
                             CUtensorMapL2promotion, CUtensorMapFloatOOBfill);

static tme_fn_t get_encoder() {
    static tme_fn_t fn = nullptr;
    if (!fn) {
        void* p = nullptr;
        cudaDriverEntryPointQueryResult st;
#if CUDART_VERSION >= 12050
        cudaGetDriverEntryPointByVersion("cuTensorMapEncodeTiled", &p, 12000,
                                         cudaEnableDefault, &st);
#else
        cudaGetDriverEntryPoint("cuTensorMapEncodeTiled", &p, cudaEnableDefault, &st);
#endif
        fn = (tme_fn_t)p;
    }
    return fn;
}

// ---------- launch ----------
extern "C" void kernel_launch(void* const* d_in, const int* in_sizes, int n_in,
                              void* d_out, int out_size) {
    const float* x  = (const float*)d_in[0];
    const int*   ei = (const int*)  d_in[1];
    const float* W1 = (const float*)d_in[2];
    const float* b1 = (const float*)d_in[3];
    const float* W2 = (const float*)d_in[4];
    const float* b2 = (const float*)d_in[5];

    int n = in_sizes[0] / FIN;
    int E = in_sizes[1] / 2;
    const int* src = ei;
    const int* dst = ei + E;

    // TMA descriptor for x: [FIN contiguous] x [n rows], box [KT,128], SW128
    CUtensorMap tmap;
    {
        cuuint64_t dims[2]    = {(cuuint64_t)FIN, (cuuint64_t)n};
        cuuint64_t strides[1] = {(cuuint64_t)FIN * 4};
        cuuint32_t box[2]     = {KT, XROWS};
        cuuint32_t es[2]      = {1, 1};
        get_encoder()(&tmap, CU_TENSOR_MAP_DATA_TYPE_FLOAT32, 2, (void*)x,
                      dims, strides, box, es,
                      CU_TENSOR_MAP_INTERLEAVE_NONE, CU_TENSOR_MAP_SWIZZLE_128B,
                      CU_TENSOR_MAP_L2_PROMOTION_L2_128B,
                      CU_TENSOR_MAP_FLOAT_OOB_FILL_NONE);
    }

    const int TB = 256;
    int gInit  = (n * HID + TB - 1) / TB;
    int gEdge  = (E + TB - 1) / TB;
    int gEdge4 = (4 * E + TB - 1) / TB;
    int gEdge2 = (2 * E + TB - 1) / TB;
    int gNode  = (n + TB - 1) / TB;
    int gXform = (n + XROWS - 1) / XROWS;

    static int smem_set = 0;
    if (!smem_set) {
        cudaFuncSetAttribute(k_xform, cudaFuncAttributeMaxDynamicSharedMemorySize, XSMEM);
        smem_set = 1;
    }

    k_init <<<gInit,  TB>>>(n);
    k_deg  <<<gEdge,  TB>>>(dst, E);
    k_dinv <<<gNode,  TB>>>(n);
    k_xform<<<gXform, XB, XSMEM>>>(tmap, W1, n);
    k_agg1 <<<gEdge4, TB>>>(src, dst, E);
    k_mid  <<<gNode,  TB>>>(W2, b1, n);
    k_agg2 <<<gEdge2, TB>>>(src, dst, E);
    k_final<<<gNode,  TB>>>(b2, (float*)d_out, n);
}